// round 13
// baseline (speedup 1.0000x reference)
#include <cuda_runtime.h>
#include <cuda_bf16.h>
#include <cstdint>

// ---------------- problem constants ----------------
#define T_STEPS 200
#define BATCH   256
#define RES     2048
#define OUTD    2
#define BETA    0.9f
#define THRESH  1.0f
#define SPK_ELEMS ((size_t)T_STEPS * BATCH * RES)
#define NSPLIT 3

// GEMM tiling: CTA 64(M) x 64(N), k-chunk 64, 512 threads = 16 warps:
// 2 k-groups x (2x4 grid of 32(M) x 16(N) warp tiles). Each k-group covers
// 2 of the 4 k16 slices per chunk -> per SMSP totals unchanged vs the 8-warp
// layout (96 MMA + 40 LDSM per chunk) but spread over 4 warps for latency
// hiding. k-group partials merged via padded smem; epilogue split by m-half.
// Persistent kernel: one CTA/SM, grid barrier between steps, V in registers.
// Split rings: A 4 x 8KB, B 6 x 24KB (B static -> prefetched across barrier).
#define BM 64
#define BN 64
#define BK 64
#define KCHUNKS (RES / BK)              // 32
#define ROW_BYTES 4096                  // 2048 bf16 per row
#define A_STAGE 8192
#define B_STAGE 24576
#define NB_STAGE 6
#define SMEM_DYN (4 * A_STAGE + NB_STAGE * B_STAGE)   // 180224
#define NBLK 128                        // grid size (<= SM count, co-resident)

// ---------------- device state ----------------
__device__ __nv_bfloat16 g_S[2 * BATCH * RES];                    // spike double buffer
__device__ __nv_bfloat16 g_W3[(size_t)NSPLIT * RES * RES];        // split W, [s][n][k]
__device__ unsigned g_bar_arrive;
__device__ unsigned g_bar_gen;

// ---------------- helpers ----------------
__device__ __forceinline__ uint32_t smem_u32(const void* p) {
    uint32_t a;
    asm("{ .reg .u64 t; cvta.to.shared.u64 t, %1; cvt.u32.u64 %0, t; }" : "=r"(a) : "l"(p));
    return a;
}

__device__ __forceinline__ void ldsm4(uint32_t* r, uint32_t addr) {
    asm volatile("ldmatrix.sync.aligned.m8n8.x4.shared.b16 {%0,%1,%2,%3}, [%4];"
                 : "=r"(r[0]), "=r"(r[1]), "=r"(r[2]), "=r"(r[3]) : "r"(addr));
}

__device__ __forceinline__ void mma16816(float* c, const uint32_t* a, uint32_t b0, uint32_t b1) {
    asm volatile("mma.sync.aligned.m16n8k16.row.col.f32.bf16.bf16.f32 "
                 "{%0,%1,%2,%3}, {%4,%5,%6,%7}, {%8,%9}, {%0,%1,%2,%3};"
                 : "+f"(c[0]), "+f"(c[1]), "+f"(c[2]), "+f"(c[3])
                 : "r"(a[0]), "r"(a[1]), "r"(a[2]), "r"(a[3]), "r"(b0), "r"(b1));
}

#define CP_COMMIT() asm volatile("cp.async.commit_group;" ::: "memory")
#define CP_WAIT2()  asm volatile("cp.async.wait_group 2;" ::: "memory")

// Grid barrier (split phases fused). Safe: 128 CTAs, 1/SM, all co-resident.
__device__ __forceinline__ void grid_barrier() {
    __syncthreads();
    if (threadIdx.x == 0) {
        unsigned gen;
        asm volatile("ld.acquire.gpu.global.u32 %0, [%1];" : "=r"(gen) : "l"(&g_bar_gen));
        unsigned prev;
        asm volatile("atom.add.release.gpu.global.u32 %0, [%1], %2;"
                     : "=r"(prev) : "l"(&g_bar_arrive), "r"(1u));
        if (prev == NBLK - 1) {
            asm volatile("st.relaxed.gpu.global.u32 [%0], %1;" :: "l"(&g_bar_arrive), "r"(0u));
            asm volatile("red.release.gpu.global.add.u32 [%0], %1;" :: "l"(&g_bar_gen), "r"(1u));
        } else {
            unsigned cur;
            do {
                asm volatile("ld.acquire.gpu.global.u32 %0, [%1];" : "=r"(cur) : "l"(&g_bar_gen));
            } while (cur == gen);
        }
    }
    __syncthreads();
}

// 64x64 bf16 tile (8KB): rows of 128B = 8 x 16B chunks, chunk ^= row%8 swizzle.
// 512 threads, 1 x 16B cp.async each.
__device__ __forceinline__ void load_tile512(uint32_t sbase, const char* g) {
    const int c = threadIdx.x;           // 0..511
    const int row = c >> 3, ch = c & 7;
    uint32_t dst = sbase + row * 128 + ((ch ^ (row & 7)) << 4);
    const char* src = g + (size_t)row * ROW_BYTES + ch * 16;
    asm volatile("cp.async.cg.shared.global [%0], [%1], 16;" :: "r"(dst), "l"(src));
}

// load B for one chunk (3 split tiles) into one B stage
__device__ __forceinline__ void load_B(uint32_t stage, const char* gB, int chunk, size_t sstr) {
    #pragma unroll
    for (int s = 0; s < NSPLIT; s++)
        load_tile512(stage + s * A_STAGE, gB + (size_t)s * sstr + (size_t)chunk * 128);
}

// ---------------------------------------------------------------------------
__global__ void init_kernel() {
    if (threadIdx.x == 0) { g_bar_arrive = 0u; g_bar_gen = 0u; }
}

// split+transpose W: g_W3[s][n][k] = bf16 split s of W[k][n]
__global__ void split_kernel(const float* __restrict__ W) {
    __shared__ float sh[32][33];
    const int k0 = blockIdx.x * 32;
    const int n0 = blockIdx.y * 32;
    const int tx = threadIdx.x;
    const int ty = threadIdx.y;
    #pragma unroll
    for (int i = ty; i < 32; i += 8)
        sh[i][tx] = W[(size_t)(k0 + i) * RES + n0 + tx];
    __syncthreads();
    #pragma unroll
    for (int i = ty; i < 32; i += 8) {
        float w = sh[tx][i];  // = W[k0+tx][n0+i]
        __nv_bfloat16 b0 = __float2bfloat16(w);
        float r1 = w - __bfloat162float(b0);
        __nv_bfloat16 b1 = __float2bfloat16(r1);
        float r2 = r1 - __bfloat162float(b1);
        __nv_bfloat16 b2 = __float2bfloat16(r2);
        size_t o = (size_t)(n0 + i) * RES + k0 + tx;
        g_W3[o]                         = b0;
        g_W3[(size_t)RES * RES + o]     = b1;
        g_W3[(size_t)2 * RES * RES + o] = b2;
    }
}

// ---------------------------------------------------------------------------
// persistent reservoir kernel: all 200 timesteps, grid barrier between steps.
// ---------------------------------------------------------------------------
__global__ void __launch_bounds__(512, 1)
reservoir_kernel(const float* __restrict__ x,
                 const float* __restrict__ Win,
                 float* __restrict__ out)
{
    extern __shared__ __align__(128) char dsm[];
    __shared__ float red[2][8][32][9];   // k-group exchange, padded (18KB)

    const int tid  = threadIdx.x;
    const int lane = tid & 31;
    const int warp = tid >> 5;       // 0..15
    const int kg = warp >> 3;        // k-group 0/1
    const int wq = warp & 7;
    const int wm = wq >> 2;          // 0..1 -> m offset *32
    const int wn = wq & 3;           // 0..3 -> n offset *16
    const int n0 = blockIdx.x * BN;
    const int m0 = blockIdx.y * BM;
    const int grp  = lane >> 3;      // ldmatrix address group
    const int lrow = lane & 7;
    const int lr = lane >> 2;        // mma frag row
    const int lc = lane & 3;         // mma frag col pair

    const uint32_t sbA = smem_u32(dsm);
    const uint32_t sbB = sbA + 4 * A_STAGE;
    const char* gB = (const char*)g_W3 + (size_t)n0 * ROW_BYTES;
    const size_t SSTR = (size_t)RES * RES * 2;   // split stride (bytes)

    // this thread's 4 epilogue n-columns: wn*16 + nt*8 + lc*2 + {0,1}
    float wv[4][3];
    #pragma unroll
    for (int nt = 0; nt < 2; nt++)
        #pragma unroll
        for (int q = 0; q < 2; q++) {
            const int nl = wn * 16 + nt * 8 + lc * 2 + q;
            wv[nt * 2 + q][0] = Win[(n0 + nl) * 3 + 0];
            wv[nt * 2 + q][1] = Win[(n0 + nl) * 3 + 1];
            wv[nt * 2 + q][2] = Win[(n0 + nl) * 3 + 2];
        }

    // ldmatrix per-thread row bases (constant across steps)
    const int rowA0 = wm * 32 + (grp & 1) * 8 + lrow;
    const int rowA1 = rowA0 + 16;
    const int rowB  = wn * 16 + (grp >> 1) * 8 + lrow;
    const uint32_t aOff0 = rowA0 * 128, aOff1 = rowA1 * 128, bOff = rowB * 128;
    const int a7_0 = rowA0 & 7, a7_1 = rowA1 & 7, b7 = rowB & 7;
    const int akh = grp >> 1, bkh = grp & 1;

    // membrane potential in registers for OWNED m16-half (mi == kg):
    // V[r][nt][2]
    float V[2][2][2];
    #pragma unroll
    for (int a = 0; a < 2; a++)
        #pragma unroll
        for (int b = 0; b < 2; b++)
            V[a][b][0] = V[a][b][1] = 0.0f;

    // preload B chunks 0..4 into B slots 0..4 (5 groups)
    #pragma unroll
    for (int p = 0; p < 5; p++) {
        load_B(sbB + p * B_STAGE, gB, p, SSTR);
        CP_COMMIT();
    }

    int bslot = 0;  // continuous B ring cursor (mod 6)

    #pragma unroll 1
    for (int t = 0; t < T_STEPS; t++) {
        float acc[2][2][4];   // [m16 tile][n8 tile][frag], this k-group's partial
        #pragma unroll
        for (int a = 0; a < 2; a++)
            #pragma unroll
            for (int b = 0; b < 2; b++)
                #pragma unroll
                for (int c = 0; c < 4; c++) acc[a][b][c] = 0.0f;

        if (t > 0) {
            const char* gA = (const char*)g_S
                + (size_t)((t + 1) & 1) * BATCH * RES * 2 + (size_t)m0 * ROW_BYTES;

            #pragma unroll 1
            for (int c = 0; c < KCHUNKS; c++) {
                CP_WAIT2();
                __syncthreads();

                const uint32_t aT = sbA + (c & 3) * A_STAGE;
                const uint32_t bT = sbB + bslot * B_STAGE;

                #pragma unroll
                for (int kq = 0; kq < 2; kq++) {
                    const int kk = kg * 2 + kq;   // this k-group's k16 slice
                    uint32_t a0[4], a1[4];
                    ldsm4(a0, aT + aOff0 + ((((kk << 1) | akh) ^ a7_0) << 4));
                    ldsm4(a1, aT + aOff1 + ((((kk << 1) | akh) ^ a7_1) << 4));
                    #pragma unroll
                    for (int s = 0; s < NSPLIT; s++) {
                        uint32_t bb[4];
                        ldsm4(bb, bT + s * A_STAGE + bOff + ((((kk << 1) | bkh) ^ b7) << 4));
                        // bb: {kLo(n8 lo), kHi(n8 lo), kLo(n8 hi), kHi(n8 hi)}
                        mma16816(acc[0][0], a0, bb[0], bb[1]);
                        mma16816(acc[0][1], a0, bb[2], bb[3]);
                        mma16816(acc[1][0], a1, bb[0], bb[1]);
                        mma16816(acc[1][1], a1, bb[2], bb[3]);
                    }
                }

                // prefetch: A distance 3 (same step only), B distance 5
                // (continuous — at c>=27 this preloads NEXT step's B chunks)
                const int an = c + 3;
                if (an < KCHUNKS)
                    load_tile512(sbA + (an & 3) * A_STAGE, gA + (size_t)an * 128);
                int bn = c + 5; if (bn >= KCHUNKS) bn -= KCHUNKS;
                int ps = bslot + 5; if (ps >= NB_STAGE) ps -= NB_STAGE;
                load_B(sbB + ps * B_STAGE, gB, bn, SSTR);
                CP_COMMIT();

                bslot = (bslot + 1 == NB_STAGE) ? 0 : bslot + 1;
            }
        }

        __syncthreads();

        // ---- k-group exchange: each kg ships its NON-owned m16-half ----
        {
            float* w = &red[kg][wq][lane][0];
            const int other = kg ^ 1;
            #pragma unroll
            for (int nt = 0; nt < 2; nt++)
                #pragma unroll
                for (int j = 0; j < 4; j++)
                    w[nt * 4 + j] = acc[other][nt][j];
        }
        __syncthreads();
        {
            const float* r = &red[kg ^ 1][wq][lane][0];
            #pragma unroll
            for (int nt = 0; nt < 2; nt++)
                #pragma unroll
                for (int j = 0; j < 4; j++)
                    acc[kg][nt][j] += r[nt * 4 + j];
        }

        // ---- fused LIF epilogue on OWNED m16-half (mi == kg) ----
        const float* xt = x + (size_t)t * BATCH * 3;
        float*         outT = out + (size_t)t * BATCH * RES;
        __nv_bfloat16* Sw   = g_S + (size_t)(t & 1) * BATCH * RES;

        #pragma unroll
        for (int r = 0; r < 2; r++) {
            const int b = m0 + wm * 32 + kg * 16 + r * 8 + lr;
            const float x0 = xt[b * 3 + 0];
            const float x1 = xt[b * 3 + 1];
            const float x2 = xt[b * 3 + 2];
            #pragma unroll
            for (int nt = 0; nt < 2; nt++) {
                const int nl = wn * 16 + nt * 8 + lc * 2;
                const size_t vi = (size_t)b * RES + n0 + nl;
                const float inj0 = x0 * wv[nt * 2 + 0][0] + x1 * wv[nt * 2 + 0][1] + x2 * wv[nt * 2 + 0][2];
                const float inj1 = x0 * wv[nt * 2 + 1][0] + x1 * wv[nt * 2 + 1][1] + x2 * wv[nt * 2 + 1][2];
                const float y0 = BETA * V[r][nt][0] + inj0 + acc[kg][nt][r * 2 + 0];
                const float y1 = BETA * V[r][nt][1] + inj1 + acc[kg][nt][r * 2 + 1];
                const float s0 = (y0 >= THRESH) ? 1.0f : 0.0f;
                const float s1 = (y1 >= THRESH) ? 1.0f : 0.0f;
                V[r][nt][0] = (y0 >= THRESH) ? 0.0f : y0;
                V[r][nt][1] = (y1 >= THRESH) ? 0.0f : y1;
                float2 sp; sp.x = s0; sp.y = s1;
                *(float2*)&outT[vi] = sp;
                __nv_bfloat162 sb2;
                sb2.x = __float2bfloat16(s0);
                sb2.y = __float2bfloat16(s1);
                *(__nv_bfloat162*)&Sw[vi] = sb2;
            }
        }

        if (t < T_STEPS - 1) {
            // spikes of step t must be visible to all CTAs before step t+1
            grid_barrier();
            // post-barrier: only A chunks 0..2 stand before the first MMA
            const char* gA2 = (const char*)g_S
                + (size_t)(t & 1) * BATCH * RES * 2 + (size_t)m0 * ROW_BYTES;
            #pragma unroll
            for (int p = 0; p < 3; p++) {
                load_tile512(sbA + p * A_STAGE, gA2 + (size_t)p * 128);
                CP_COMMIT();
            }
        }
    }
}

// ---------------------------------------------------------------------------
__global__ void __launch_bounds__(256)
logits_kernel(const float* __restrict__ spk,
              const float* __restrict__ Wout,
              float* __restrict__ logits)
{
    const int b = blockIdx.x;
    const int tid = threadIdx.x;
    float p0 = 0.0f, p1 = 0.0f;
    for (int r = tid; r < RES; r += 256) {
        float s = 0.0f;
        #pragma unroll
        for (int tt = 0; tt < 10; tt++)
            s += spk[((size_t)(T_STEPS - 10 + tt) * BATCH + b) * RES + r];
        s *= 0.1f;
        p0 = fmaf(s, Wout[r], p0);
        p1 = fmaf(s, Wout[RES + r], p1);
    }
    __shared__ float sh0[256];
    __shared__ float sh1[256];
    sh0[tid] = p0; sh1[tid] = p1;
    __syncthreads();
    for (int off = 128; off > 0; off >>= 1) {
        if (tid < off) { sh0[tid] += sh0[tid + off]; sh1[tid] += sh1[tid + off]; }
        __syncthreads();
    }
    if (tid == 0) {
        logits[b * OUTD + 0] = sh0[0];
        logits[b * OUTD + 1] = sh1[0];
    }
}

// ---------------------------------------------------------------------------
extern "C" void kernel_launch(void* const* d_in, const int* in_sizes, int n_in,
                              void* d_out, int out_size)
{
    const float* x    = (const float*)d_in[0];  // [200, 256, 3]
    const float* W    = (const float*)d_in[1];  // [2048, 2048]
    const float* Win  = (const float*)d_in[2];  // [2048, 3]
    const float* Wout = (const float*)d_in[3];  // [2, 2048]
    float* out = (float*)d_out;                 // spk [200*256*2048] | logits [256*2]

    cudaFuncSetAttribute(reservoir_kernel, cudaFuncAttributeMaxDynamicSharedMemorySize, SMEM_DYN);

    init_kernel<<<1, 32>>>();
    split_kernel<<<dim3(RES / 32, RES / 32), dim3(32, 8)>>>(W);

    dim3 grid(RES / BN, BATCH / BM);  // (32, 4) = 128 CTAs, all co-resident
    reservoir_kernel<<<grid, 512, SMEM_DYN>>>(x, Win, out);

    logits_kernel<<<BATCH, 256>>>(out, Wout, out + SPK_ELEMS);
}

// round 14
// speedup vs baseline: 1.0775x; 1.0775x over previous
#include <cuda_runtime.h>
#include <cuda_bf16.h>
#include <cstdint>

// ---------------- problem constants ----------------
#define T_STEPS 200
#define BATCH   256
#define RES     2048
#define OUTD    2
#define BETA    0.9f
#define THRESH  1.0f
#define SPK_ELEMS ((size_t)T_STEPS * BATCH * RES)
#define NSPLIT 3

// GEMM tiling: CTA 64(M) x 64(N), k-chunk 64, 256 threads (8 warps, 2x4),
// warp tile 32(M) x 16(N), mma.sync m16n8k16 bf16  (R8 champion layout).
// Pipeline: unified 6-slot ring, slot = 8KB A + 24KB B (32KB). TWO chunks
// per iteration (superchunk): one wait_group+syncthreads+commit per super
// -> 16 syncs/step instead of 32. Continuous slot counter mod 6 across
// steps; B (static W) prefetched across the grid barrier.
// Persistent kernel: one CTA/SM, grid barrier between steps, V in registers.
#define BM 64
#define BN 64
#define BK 64
#define KCHUNKS (RES / BK)              // 32
#define NSUPER (KCHUNKS / 2)            // 16
#define ROW_BYTES 4096                  // 2048 bf16 per row
#define A_STAGE 8192
#define B_STAGE 24576
#define NSLOT 6
#define SMEM_DYN (NSLOT * (A_STAGE + B_STAGE))   // 196608
#define NBLK 128                        // grid size (<= SM count, co-resident)

// ---------------- device state ----------------
__device__ __nv_bfloat16 g_S[2 * BATCH * RES];                    // spike double buffer
__device__ __nv_bfloat16 g_W3[(size_t)NSPLIT * RES * RES];        // split W, [s][n][k]
__device__ unsigned g_bar_arrive;
__device__ unsigned g_bar_gen;

// ---------------- helpers ----------------
__device__ __forceinline__ uint32_t smem_u32(const void* p) {
    uint32_t a;
    asm("{ .reg .u64 t; cvta.to.shared.u64 t, %1; cvt.u32.u64 %0, t; }" : "=r"(a) : "l"(p));
    return a;
}

__device__ __forceinline__ void ldsm4(uint32_t* r, uint32_t addr) {
    asm volatile("ldmatrix.sync.aligned.m8n8.x4.shared.b16 {%0,%1,%2,%3}, [%4];"
                 : "=r"(r[0]), "=r"(r[1]), "=r"(r[2]), "=r"(r[3]) : "r"(addr));
}

__device__ __forceinline__ void mma16816(float* c, const uint32_t* a, uint32_t b0, uint32_t b1) {
    asm volatile("mma.sync.aligned.m16n8k16.row.col.f32.bf16.bf16.f32 "
                 "{%0,%1,%2,%3}, {%4,%5,%6,%7}, {%8,%9}, {%0,%1,%2,%3};"
                 : "+f"(c[0]), "+f"(c[1]), "+f"(c[2]), "+f"(c[3])
                 : "r"(a[0]), "r"(a[1]), "r"(a[2]), "r"(a[3]), "r"(b0), "r"(b1));
}

#define CP_COMMIT() asm volatile("cp.async.commit_group;" ::: "memory")
#define CP_WAIT1()  asm volatile("cp.async.wait_group 1;" ::: "memory")

// Grid barrier. Safe: 128 CTAs, 1/SM, all co-resident.
__device__ __forceinline__ void grid_barrier() {
    __syncthreads();
    if (threadIdx.x == 0) {
        unsigned gen;
        asm volatile("ld.acquire.gpu.global.u32 %0, [%1];" : "=r"(gen) : "l"(&g_bar_gen));
        unsigned prev;
        asm volatile("atom.add.release.gpu.global.u32 %0, [%1], %2;"
                     : "=r"(prev) : "l"(&g_bar_arrive), "r"(1u));
        if (prev == NBLK - 1) {
            asm volatile("st.relaxed.gpu.global.u32 [%0], %1;" :: "l"(&g_bar_arrive), "r"(0u));
            asm volatile("red.release.gpu.global.add.u32 [%0], %1;" :: "l"(&g_bar_gen), "r"(1u));
        } else {
            unsigned cur;
            do {
                asm volatile("ld.acquire.gpu.global.u32 %0, [%1];" : "=r"(cur) : "l"(&g_bar_gen));
            } while (cur == gen);
        }
    }
    __syncthreads();
}

// 64x64 bf16 tile (8KB): rows of 128B = 8 x 16B chunks, chunk ^= row%8 swizzle.
// 256 threads, 2 x 16B cp.async each.
__device__ __forceinline__ void load_tile256(uint32_t sbase, const char* g) {
    const int tid = threadIdx.x;
    #pragma unroll
    for (int i = 0; i < 2; i++) {
        int c = tid + i * 256;
        int row = c >> 3, ch = c & 7;
        uint32_t dst = sbase + row * 128 + ((ch ^ (row & 7)) << 4);
        const char* src = g + (size_t)row * ROW_BYTES + ch * 16;
        asm volatile("cp.async.cg.shared.global [%0], [%1], 16;" :: "r"(dst), "l"(src));
    }
}

// load B for one chunk (3 split tiles) into one B slot
__device__ __forceinline__ void load_B(uint32_t stage, const char* gB, int chunk, size_t sstr) {
    #pragma unroll
    for (int s = 0; s < NSPLIT; s++)
        load_tile256(stage + s * A_STAGE, gB + (size_t)s * sstr + (size_t)chunk * 128);
}

// ---------------------------------------------------------------------------
__global__ void init_kernel() {
    if (threadIdx.x == 0) { g_bar_arrive = 0u; g_bar_gen = 0u; }
}

// split+transpose W: g_W3[s][n][k] = bf16 split s of W[k][n]
__global__ void split_kernel(const float* __restrict__ W) {
    __shared__ float sh[32][33];
    const int k0 = blockIdx.x * 32;
    const int n0 = blockIdx.y * 32;
    const int tx = threadIdx.x;
    const int ty = threadIdx.y;
    #pragma unroll
    for (int i = ty; i < 32; i += 8)
        sh[i][tx] = W[(size_t)(k0 + i) * RES + n0 + tx];
    __syncthreads();
    #pragma unroll
    for (int i = ty; i < 32; i += 8) {
        float w = sh[tx][i];  // = W[k0+tx][n0+i]
        __nv_bfloat16 b0 = __float2bfloat16(w);
        float r1 = w - __bfloat162float(b0);
        __nv_bfloat16 b1 = __float2bfloat16(r1);
        float r2 = r1 - __bfloat162float(b1);
        __nv_bfloat16 b2 = __float2bfloat16(r2);
        size_t o = (size_t)(n0 + i) * RES + k0 + tx;
        g_W3[o]                         = b0;
        g_W3[(size_t)RES * RES + o]     = b1;
        g_W3[(size_t)2 * RES * RES + o] = b2;
    }
}

// ---------------------------------------------------------------------------
// persistent reservoir kernel: all 200 timesteps, grid barrier between steps.
// ---------------------------------------------------------------------------
__global__ void __launch_bounds__(256, 1)
reservoir_kernel(const float* __restrict__ x,
                 const float* __restrict__ Win,
                 float* __restrict__ out)
{
    extern __shared__ __align__(128) char dsm[];

    const int tid  = threadIdx.x;
    const int lane = tid & 31;
    const int warp = tid >> 5;
    const int n0 = blockIdx.x * BN;
    const int m0 = blockIdx.y * BM;
    const int wm = warp >> 2;        // 0..1 -> m offset *32
    const int wn = warp & 3;         // 0..3 -> n offset *16
    const int grp  = lane >> 3;      // ldmatrix address group
    const int lrow = lane & 7;
    const int lr = lane >> 2;        // mma frag row
    const int lc = lane & 3;         // mma frag col pair

    const uint32_t sbA = smem_u32(dsm);                 // 6 x 8KB A slots
    const uint32_t sbB = sbA + NSLOT * A_STAGE;         // 6 x 24KB B slots
    const char* gB = (const char*)g_W3 + (size_t)n0 * ROW_BYTES;
    const size_t SSTR = (size_t)RES * RES * 2;   // split stride (bytes)

    // this thread's 4 epilogue n-columns: wn*16 + nt*8 + lc*2 + {0,1}
    float wv[4][3];
    #pragma unroll
    for (int nt = 0; nt < 2; nt++)
        #pragma unroll
        for (int q = 0; q < 2; q++) {
            const int nl = wn * 16 + nt * 8 + lc * 2 + q;
            wv[nt * 2 + q][0] = Win[(n0 + nl) * 3 + 0];
            wv[nt * 2 + q][1] = Win[(n0 + nl) * 3 + 1];
            wv[nt * 2 + q][2] = Win[(n0 + nl) * 3 + 2];
        }

    // ldmatrix per-thread row bases (constant across steps)
    const int rowA0 = wm * 32 + (grp & 1) * 8 + lrow;
    const int rowA1 = rowA0 + 16;
    const int rowB  = wn * 16 + (grp >> 1) * 8 + lrow;
    const uint32_t aOff0 = rowA0 * 128, aOff1 = rowA1 * 128, bOff = rowB * 128;
    const int a7_0 = rowA0 & 7, a7_1 = rowA1 & 7, b7 = rowB & 7;
    const int akh = grp >> 1, bkh = grp & 1;

    // membrane potential in registers: V[mi][r][nt][2]
    float V[2][2][2][2];
    #pragma unroll
    for (int a = 0; a < 2; a++)
        #pragma unroll
        for (int b = 0; b < 2; b++)
            #pragma unroll
            for (int c = 0; c < 2; c++)
                V[a][b][c][0] = V[a][b][c][1] = 0.0f;

    // initial preload: B chunks 0..3 into slots 0..3, two groups of two
    load_B(sbB + 0 * B_STAGE, gB, 0, SSTR);
    load_B(sbB + 1 * B_STAGE, gB, 1, SSTR);
    CP_COMMIT();
    load_B(sbB + 2 * B_STAGE, gB, 2, SSTR);
    load_B(sbB + 3 * B_STAGE, gB, 3, SSTR);
    CP_COMMIT();

    int slotc = 0;  // slot of the next chunk to compute; continuous mod 6

    #pragma unroll 1
    for (int t = 0; t < T_STEPS; t++) {
        float acc[2][2][4];
        #pragma unroll
        for (int a = 0; a < 2; a++)
            #pragma unroll
            for (int b = 0; b < 2; b++)
                #pragma unroll
                for (int c = 0; c < 4; c++) acc[a][b][c] = 0.0f;

        if (t > 0) {
            const char* gA = (const char*)g_S
                + (size_t)((t + 1) & 1) * BATCH * RES * 2 + (size_t)m0 * ROW_BYTES;

            #pragma unroll 1
            for (int s = 0; s < NSUPER; s++) {
                CP_WAIT1();
                __syncthreads();

                // ---- compute two chunks ----
                #pragma unroll
                for (int cc = 0; cc < 2; cc++) {
                    int sl = slotc + cc; if (sl >= NSLOT) sl -= NSLOT;
                    const uint32_t aT = sbA + sl * A_STAGE;
                    const uint32_t bT = sbB + sl * B_STAGE;

                    #pragma unroll
                    for (int kk = 0; kk < 4; kk++) {
                        uint32_t a0[4], a1[4];
                        ldsm4(a0, aT + aOff0 + ((((kk << 1) | akh) ^ a7_0) << 4));
                        ldsm4(a1, aT + aOff1 + ((((kk << 1) | akh) ^ a7_1) << 4));
                        #pragma unroll
                        for (int sp = 0; sp < NSPLIT; sp++) {
                            uint32_t bb[4];
                            ldsm4(bb, bT + sp * A_STAGE + bOff + ((((kk << 1) | bkh) ^ b7) << 4));
                            mma16816(acc[0][0], a0, bb[0], bb[1]);
                            mma16816(acc[0][1], a0, bb[2], bb[3]);
                            mma16816(acc[1][0], a1, bb[0], bb[1]);
                            mma16816(acc[1][1], a1, bb[2], bb[3]);
                        }
                    }
                }

                // ---- prefetch chunks 2s+4, 2s+5 (A same-step only; B wraps
                //      into next step — W is static) ----
                const int c2 = 2 * s;
                #pragma unroll
                for (int cc = 0; cc < 2; cc++) {
                    const int cn = c2 + 4 + cc;
                    int sl = slotc + 4 + cc; if (sl >= NSLOT) sl -= NSLOT;
                    if (cn < KCHUNKS)
                        load_tile256(sbA + sl * A_STAGE, gA + (size_t)cn * 128);
                    int bn = cn; if (bn >= KCHUNKS) bn -= KCHUNKS;
                    load_B(sbB + sl * B_STAGE, gB, bn, SSTR);
                }
                CP_COMMIT();

                slotc += 2; if (slotc >= NSLOT) slotc -= NSLOT;
            }
        }

        __syncthreads();

        // ---- fused LIF epilogue (V in registers, Win in registers) ----
        const float* xt = x + (size_t)t * BATCH * 3;
        float*         outT = out + (size_t)t * BATCH * RES;
        __nv_bfloat16* Sw   = g_S + (size_t)(t & 1) * BATCH * RES;

        #pragma unroll
        for (int mi = 0; mi < 2; mi++) {
            #pragma unroll
            for (int r = 0; r < 2; r++) {
                const int b = m0 + wm * 32 + mi * 16 + r * 8 + lr;
                const float x0 = xt[b * 3 + 0];
                const float x1 = xt[b * 3 + 1];
                const float x2 = xt[b * 3 + 2];
                #pragma unroll
                for (int nt = 0; nt < 2; nt++) {
                    const int nl = wn * 16 + nt * 8 + lc * 2;
                    const size_t vi = (size_t)b * RES + n0 + nl;
                    const float inj0 = x0 * wv[nt * 2 + 0][0] + x1 * wv[nt * 2 + 0][1] + x2 * wv[nt * 2 + 0][2];
                    const float inj1 = x0 * wv[nt * 2 + 1][0] + x1 * wv[nt * 2 + 1][1] + x2 * wv[nt * 2 + 1][2];
                    const float y0 = BETA * V[mi][r][nt][0] + inj0 + acc[mi][nt][r * 2 + 0];
                    const float y1 = BETA * V[mi][r][nt][1] + inj1 + acc[mi][nt][r * 2 + 1];
                    const float s0 = (y0 >= THRESH) ? 1.0f : 0.0f;
                    const float s1 = (y1 >= THRESH) ? 1.0f : 0.0f;
                    V[mi][r][nt][0] = (y0 >= THRESH) ? 0.0f : y0;
                    V[mi][r][nt][1] = (y1 >= THRESH) ? 0.0f : y1;
                    float2 sp; sp.x = s0; sp.y = s1;
                    *(float2*)&outT[vi] = sp;
                    __nv_bfloat162 sb2;
                    sb2.x = __float2bfloat16(s0);
                    sb2.y = __float2bfloat16(s1);
                    *(__nv_bfloat162*)&Sw[vi] = sb2;
                }
            }
        }

        if (t < T_STEPS - 1) {
            // spikes of step t must be visible to all CTAs before step t+1
            grid_barrier();
            // post-barrier: next step's A chunks 0..3 into slots slotc..+3,
            // two groups of two (matches steady-state group accounting)
            const char* gA2 = (const char*)g_S
                + (size_t)(t & 1) * BATCH * RES * 2 + (size_t)m0 * ROW_BYTES;
            #pragma unroll
            for (int pg = 0; pg < 2; pg++) {
                #pragma unroll
                for (int q = 0; q < 2; q++) {
                    const int p = pg * 2 + q;
                    int sl = slotc + p; if (sl >= NSLOT) sl -= NSLOT;
                    load_tile256(sbA + sl * A_STAGE, gA2 + (size_t)p * 128);
                }
                CP_COMMIT();
            }
        }
    }
}

// ---------------------------------------------------------------------------
__global__ void __launch_bounds__(256)
logits_kernel(const float* __restrict__ spk,
              const float* __restrict__ Wout,
              float* __restrict__ logits)
{
    const int b = blockIdx.x;
    const int tid = threadIdx.x;
    float p0 = 0.0f, p1 = 0.0f;
    for (int r = tid; r < RES; r += 256) {
        float s = 0.0f;
        #pragma unroll
        for (int tt = 0; tt < 10; tt++)
            s += spk[((size_t)(T_STEPS - 10 + tt) * BATCH + b) * RES + r];
        s *= 0.1f;
        p0 = fmaf(s, Wout[r], p0);
        p1 = fmaf(s, Wout[RES + r], p1);
    }
    __shared__ float sh0[256];
    __shared__ float sh1[256];
    sh0[tid] = p0; sh1[tid] = p1;
    __syncthreads();
    for (int off = 128; off > 0; off >>= 1) {
        if (tid < off) { sh0[tid] += sh0[tid + off]; sh1[tid] += sh1[tid + off]; }
        __syncthreads();
    }
    if (tid == 0) {
        logits[b * OUTD + 0] = sh0[0];
        logits[b * OUTD + 1] = sh1[0];
    }
}

// ---------------------------------------------------------------------------
extern "C" void kernel_launch(void* const* d_in, const int* in_sizes, int n_in,
                              void* d_out, int out_size)
{
    const float* x    = (const float*)d_in[0];  // [200, 256, 3]
    const float* W    = (const float*)d_in[1];  // [2048, 2048]
    const float* Win  = (const float*)d_in[2];  // [2048, 3]
    const float* Wout = (const float*)d_in[3];  // [2, 2048]
    float* out = (float*)d_out;                 // spk [200*256*2048] | logits [256*2]

    cudaFuncSetAttribute(reservoir_kernel, cudaFuncAttributeMaxDynamicSharedMemorySize, SMEM_DYN);

    init_kernel<<<1, 32>>>();
    split_kernel<<<dim3(RES / 32, RES / 32), dim3(32, 8)>>>(W);

    dim3 grid(RES / BN, BATCH / BM);  // (32, 4) = 128 CTAs, all co-resident
    reservoir_kernel<<<grid, 256, SMEM_DYN>>>(x, Win, out);

    logits_kernel<<<BATCH, 256>>>(out, Wout, out + SPK_ELEMS);
}

// round 15
// speedup vs baseline: 1.1385x; 1.0566x over previous
#include <cuda_runtime.h>
#include <cuda_bf16.h>
#include <cstdint>

// ---------------- problem constants ----------------
#define T_STEPS 200
#define BATCH   256
#define RES     2048
#define OUTD    2
#define BETA    0.9f
#define THRESH  1.0f
#define SPK_ELEMS ((size_t)T_STEPS * BATCH * RES)
#define NSPLIT 3

// GEMM tiling: CTA 64(M) x 64(N), k-chunk 64, 256 threads (8 warps, 2x4),
// warp tile 32(M) x 16(N), mma.sync m16n8k16 bf16  (R8 champion layout).
// Inner loop software-pipelined: fragments double-buffered across k16 slices
// so each kk's 5 LDSMs are hidden under the previous kk's 12 MMAs.
// Persistent kernel: one CTA/SM, grid barrier between steps, V in registers.
// Split rings: A 4 x 8KB, B 6 x 24KB (B static across steps -> prefetched
// ACROSS the grid barrier with a continuous mod-6 slot counter).
#define BM 64
#define BN 64
#define BK 64
#define KCHUNKS (RES / BK)              // 32
#define ROW_BYTES 4096                  // 2048 bf16 per row
#define A_STAGE 8192
#define B_STAGE 24576
#define NB_STAGE 6
#define SMEM_DYN (4 * A_STAGE + NB_STAGE * B_STAGE)   // 180224
#define NBLK 128                        // grid size (<= SM count, co-resident)

// ---------------- device state ----------------
__device__ __nv_bfloat16 g_S[2 * BATCH * RES];                    // spike double buffer
__device__ __nv_bfloat16 g_W3[(size_t)NSPLIT * RES * RES];        // split W, [s][n][k]
__device__ unsigned g_bar_arrive;
__device__ unsigned g_bar_gen;

// ---------------- helpers ----------------
__device__ __forceinline__ uint32_t smem_u32(const void* p) {
    uint32_t a;
    asm("{ .reg .u64 t; cvta.to.shared.u64 t, %1; cvt.u32.u64 %0, t; }" : "=r"(a) : "l"(p));
    return a;
}

__device__ __forceinline__ void ldsm4(uint32_t* r, uint32_t addr) {
    asm volatile("ldmatrix.sync.aligned.m8n8.x4.shared.b16 {%0,%1,%2,%3}, [%4];"
                 : "=r"(r[0]), "=r"(r[1]), "=r"(r[2]), "=r"(r[3]) : "r"(addr));
}

// NON-volatile: pure register computation; lets ptxas schedule MMAs freely
// around LDSMs (dependencies enforced by register constraints).
__device__ __forceinline__ void mma16816(float* c, const uint32_t* a, uint32_t b0, uint32_t b1) {
    asm("mma.sync.aligned.m16n8k16.row.col.f32.bf16.bf16.f32 "
        "{%0,%1,%2,%3}, {%4,%5,%6,%7}, {%8,%9}, {%0,%1,%2,%3};"
        : "+f"(c[0]), "+f"(c[1]), "+f"(c[2]), "+f"(c[3])
        : "r"(a[0]), "r"(a[1]), "r"(a[2]), "r"(a[3]), "r"(b0), "r"(b1));
}

#define CP_COMMIT() asm volatile("cp.async.commit_group;" ::: "memory")
#define CP_WAIT2()  asm volatile("cp.async.wait_group 2;" ::: "memory")

// Grid barrier. Safe: 128 CTAs, 1/SM, all co-resident.
__device__ __forceinline__ void grid_barrier() {
    __syncthreads();
    if (threadIdx.x == 0) {
        unsigned gen;
        asm volatile("ld.acquire.gpu.global.u32 %0, [%1];" : "=r"(gen) : "l"(&g_bar_gen));
        unsigned prev;
        asm volatile("atom.add.release.gpu.global.u32 %0, [%1], %2;"
                     : "=r"(prev) : "l"(&g_bar_arrive), "r"(1u));
        if (prev == NBLK - 1) {
            asm volatile("st.relaxed.gpu.global.u32 [%0], %1;" :: "l"(&g_bar_arrive), "r"(0u));
            asm volatile("red.release.gpu.global.add.u32 [%0], %1;" :: "l"(&g_bar_gen), "r"(1u));
        } else {
            unsigned cur;
            do {
                asm volatile("ld.acquire.gpu.global.u32 %0, [%1];" : "=r"(cur) : "l"(&g_bar_gen));
            } while (cur == gen);
        }
    }
    __syncthreads();
}

// 64x64 bf16 tile (8KB): rows of 128B = 8 x 16B chunks, chunk ^= row%8 swizzle.
// 256 threads, 2 x 16B cp.async each.
__device__ __forceinline__ void load_tile256(uint32_t sbase, const char* g) {
    const int tid = threadIdx.x;
    #pragma unroll
    for (int i = 0; i < 2; i++) {
        int c = tid + i * 256;
        int row = c >> 3, ch = c & 7;
        uint32_t dst = sbase + row * 128 + ((ch ^ (row & 7)) << 4);
        const char* src = g + (size_t)row * ROW_BYTES + ch * 16;
        asm volatile("cp.async.cg.shared.global [%0], [%1], 16;" :: "r"(dst), "l"(src));
    }
}

// load B for one chunk (3 split tiles) into one B stage
__device__ __forceinline__ void load_B(uint32_t stage, const char* gB, int chunk, size_t sstr) {
    #pragma unroll
    for (int s = 0; s < NSPLIT; s++)
        load_tile256(stage + s * A_STAGE, gB + (size_t)s * sstr + (size_t)chunk * 128);
}

// ---------------------------------------------------------------------------
__global__ void init_kernel() {
    if (threadIdx.x == 0) { g_bar_arrive = 0u; g_bar_gen = 0u; }
}

// split+transpose W: g_W3[s][n][k] = bf16 split s of W[k][n]
__global__ void split_kernel(const float* __restrict__ W) {
    __shared__ float sh[32][33];
    const int k0 = blockIdx.x * 32;
    const int n0 = blockIdx.y * 32;
    const int tx = threadIdx.x;
    const int ty = threadIdx.y;
    #pragma unroll
    for (int i = ty; i < 32; i += 8)
        sh[i][tx] = W[(size_t)(k0 + i) * RES + n0 + tx];
    __syncthreads();
    #pragma unroll
    for (int i = ty; i < 32; i += 8) {
        float w = sh[tx][i];  // = W[k0+tx][n0+i]
        __nv_bfloat16 b0 = __float2bfloat16(w);
        float r1 = w - __bfloat162float(b0);
        __nv_bfloat16 b1 = __float2bfloat16(r1);
        float r2 = r1 - __bfloat162float(b1);
        __nv_bfloat16 b2 = __float2bfloat16(r2);
        size_t o = (size_t)(n0 + i) * RES + k0 + tx;
        g_W3[o]                         = b0;
        g_W3[(size_t)RES * RES + o]     = b1;
        g_W3[(size_t)2 * RES * RES + o] = b2;
    }
}

// ---------------------------------------------------------------------------
// persistent reservoir kernel: all 200 timesteps, grid barrier between steps.
// ---------------------------------------------------------------------------
__global__ void __launch_bounds__(256, 1)
reservoir_kernel(const float* __restrict__ x,
                 const float* __restrict__ Win,
                 float* __restrict__ out)
{
    extern __shared__ __align__(128) char dsm[];

    const int tid  = threadIdx.x;
    const int lane = tid & 31;
    const int warp = tid >> 5;
    const int n0 = blockIdx.x * BN;
    const int m0 = blockIdx.y * BM;
    const int wm = warp >> 2;        // 0..1 -> m offset *32
    const int wn = warp & 3;         // 0..3 -> n offset *16
    const int grp  = lane >> 3;      // ldmatrix address group
    const int lrow = lane & 7;
    const int lr = lane >> 2;        // mma frag row
    const int lc = lane & 3;         // mma frag col pair

    const uint32_t sbA = smem_u32(dsm);
    const uint32_t sbB = sbA + 4 * A_STAGE;
    const char* gB = (const char*)g_W3 + (size_t)n0 * ROW_BYTES;
    const size_t SSTR = (size_t)RES * RES * 2;   // split stride (bytes)

    // this thread's 4 epilogue n-columns: wn*16 + nt*8 + lc*2 + {0,1}
    float wv[4][3];
    #pragma unroll
    for (int nt = 0; nt < 2; nt++)
        #pragma unroll
        for (int q = 0; q < 2; q++) {
            const int nl = wn * 16 + nt * 8 + lc * 2 + q;
            wv[nt * 2 + q][0] = Win[(n0 + nl) * 3 + 0];
            wv[nt * 2 + q][1] = Win[(n0 + nl) * 3 + 1];
            wv[nt * 2 + q][2] = Win[(n0 + nl) * 3 + 2];
        }

    // ldmatrix per-thread row bases (constant across steps)
    const int rowA0 = wm * 32 + (grp & 1) * 8 + lrow;
    const int rowA1 = rowA0 + 16;
    const int rowB  = wn * 16 + (grp >> 1) * 8 + lrow;
    const uint32_t aOff0 = rowA0 * 128, aOff1 = rowA1 * 128, bOff = rowB * 128;
    const int a7_0 = rowA0 & 7, a7_1 = rowA1 & 7, b7 = rowB & 7;
    const int akh = grp >> 1, bkh = grp & 1;

    // membrane potential in registers: V[mi][r][nt][2]
    float V[2][2][2][2];
    #pragma unroll
    for (int a = 0; a < 2; a++)
        #pragma unroll
        for (int b = 0; b < 2; b++)
            #pragma unroll
            for (int c = 0; c < 2; c++)
                V[a][b][c][0] = V[a][b][c][1] = 0.0f;

    // preload B chunks 0..4 into B slots 0..4 (5 groups)
    #pragma unroll
    for (int p = 0; p < 5; p++) {
        load_B(sbB + p * B_STAGE, gB, p, SSTR);
        CP_COMMIT();
    }

    int bslot = 0;  // continuous B ring cursor (mod 6)

#define A0_ADDR(kk) (aT + aOff0 + (((((kk) << 1) | akh) ^ a7_0) << 4))
#define A1_ADDR(kk) (aT + aOff1 + (((((kk) << 1) | akh) ^ a7_1) << 4))
#define B_ADDR(kk, s) (bT + (s) * A_STAGE + bOff + (((((kk) << 1) | bkh) ^ b7) << 4))

    #pragma unroll 1
    for (int t = 0; t < T_STEPS; t++) {
        float acc[2][2][4];
        #pragma unroll
        for (int a = 0; a < 2; a++)
            #pragma unroll
            for (int b = 0; b < 2; b++)
                #pragma unroll
                for (int c = 0; c < 4; c++) acc[a][b][c] = 0.0f;

        if (t > 0) {
            const char* gA = (const char*)g_S
                + (size_t)((t + 1) & 1) * BATCH * RES * 2 + (size_t)m0 * ROW_BYTES;

            #pragma unroll 1
            for (int c = 0; c < KCHUNKS; c++) {
                CP_WAIT2();
                __syncthreads();

                const uint32_t aT = sbA + (c & 3) * A_STAGE;
                const uint32_t bT = sbB + bslot * B_STAGE;

                // ---- software-pipelined compute: frags double-buffered ----
                uint32_t aF[2][2][4];   // [buf][m16 tile][frag]
                uint32_t bF[2][3][4];   // [buf][split][frag]

                // prologue: kk=0 fragments into buf 0
                ldsm4(aF[0][0], A0_ADDR(0));
                ldsm4(aF[0][1], A1_ADDR(0));
                #pragma unroll
                for (int s = 0; s < NSPLIT; s++)
                    ldsm4(bF[0][s], B_ADDR(0, s));

                #pragma unroll
                for (int kk = 0; kk < 4; kk++) {
                    const int cur = kk & 1, nxt = cur ^ 1;
                    if (kk < 3) {   // issue kk+1 loads before kk's MMAs
                        ldsm4(aF[nxt][0], A0_ADDR(kk + 1));
                        ldsm4(aF[nxt][1], A1_ADDR(kk + 1));
                        #pragma unroll
                        for (int s = 0; s < NSPLIT; s++)
                            ldsm4(bF[nxt][s], B_ADDR(kk + 1, s));
                    }
                    #pragma unroll
                    for (int s = 0; s < NSPLIT; s++) {
                        mma16816(acc[0][0], aF[cur][0], bF[cur][s][0], bF[cur][s][1]);
                        mma16816(acc[0][1], aF[cur][0], bF[cur][s][2], bF[cur][s][3]);
                        mma16816(acc[1][0], aF[cur][1], bF[cur][s][0], bF[cur][s][1]);
                        mma16816(acc[1][1], aF[cur][1], bF[cur][s][2], bF[cur][s][3]);
                    }
                }

                // prefetch: A distance 3 (same step only), B distance 5
                // (continuous — at c>=27 this preloads NEXT step's B chunks)
                const int an = c + 3;
                if (an < KCHUNKS)
                    load_tile256(sbA + (an & 3) * A_STAGE, gA + (size_t)an * 128);
                int bn = c + 5; if (bn >= KCHUNKS) bn -= KCHUNKS;
                int ps = bslot + 5; if (ps >= NB_STAGE) ps -= NB_STAGE;
                load_B(sbB + ps * B_STAGE, gB, bn, SSTR);
                CP_COMMIT();

                bslot = (bslot + 1 == NB_STAGE) ? 0 : bslot + 1;
            }
        }

        __syncthreads();

        // ---- fused LIF epilogue (V in registers, Win in registers) ----
        const float* xt = x + (size_t)t * BATCH * 3;
        float*         outT = out + (size_t)t * BATCH * RES;
        __nv_bfloat16* Sw   = g_S + (size_t)(t & 1) * BATCH * RES;

        #pragma unroll
        for (int mi = 0; mi < 2; mi++) {
            #pragma unroll
            for (int r = 0; r < 2; r++) {
                const int b = m0 + wm * 32 + mi * 16 + r * 8 + lr;
                const float x0 = xt[b * 3 + 0];
                const float x1 = xt[b * 3 + 1];
                const float x2 = xt[b * 3 + 2];
                #pragma unroll
                for (int nt = 0; nt < 2; nt++) {
                    const int nl = wn * 16 + nt * 8 + lc * 2;
                    const size_t vi = (size_t)b * RES + n0 + nl;
                    const float inj0 = x0 * wv[nt * 2 + 0][0] + x1 * wv[nt * 2 + 0][1] + x2 * wv[nt * 2 + 0][2];
                    const float inj1 = x0 * wv[nt * 2 + 1][0] + x1 * wv[nt * 2 + 1][1] + x2 * wv[nt * 2 + 1][2];
                    const float y0 = BETA * V[mi][r][nt][0] + inj0 + acc[mi][nt][r * 2 + 0];
                    const float y1 = BETA * V[mi][r][nt][1] + inj1 + acc[mi][nt][r * 2 + 1];
                    const float s0 = (y0 >= THRESH) ? 1.0f : 0.0f;
                    const float s1 = (y1 >= THRESH) ? 1.0f : 0.0f;
                    V[mi][r][nt][0] = (y0 >= THRESH) ? 0.0f : y0;
                    V[mi][r][nt][1] = (y1 >= THRESH) ? 0.0f : y1;
                    float2 sp; sp.x = s0; sp.y = s1;
                    *(float2*)&outT[vi] = sp;
                    __nv_bfloat162 sb2;
                    sb2.x = __float2bfloat16(s0);
                    sb2.y = __float2bfloat16(s1);
                    *(__nv_bfloat162*)&Sw[vi] = sb2;
                }
            }
        }

        if (t < T_STEPS - 1) {
            // spikes of step t must be visible to all CTAs before step t+1
            grid_barrier();
            // post-barrier: only A chunks 0..2 stand before the first MMA
            const char* gA2 = (const char*)g_S
                + (size_t)(t & 1) * BATCH * RES * 2 + (size_t)m0 * ROW_BYTES;
            #pragma unroll
            for (int p = 0; p < 3; p++) {
                load_tile256(sbA + p * A_STAGE, gA2 + (size_t)p * 128);
                CP_COMMIT();
            }
        }
    }
#undef A0_ADDR
#undef A1_ADDR
#undef B_ADDR
}

// ---------------------------------------------------------------------------
__global__ void __launch_bounds__(256)
logits_kernel(const float* __restrict__ spk,
              const float* __restrict__ Wout,
              float* __restrict__ logits)
{
    const int b = blockIdx.x;
    const int tid = threadIdx.x;
    float p0 = 0.0f, p1 = 0.0f;
    for (int r = tid; r < RES; r += 256) {
        float s = 0.0f;
        #pragma unroll
        for (int tt = 0; tt < 10; tt++)
            s += spk[((size_t)(T_STEPS - 10 + tt) * BATCH + b) * RES + r];
        s *= 0.1f;
        p0 = fmaf(s, Wout[r], p0);
        p1 = fmaf(s, Wout[RES + r], p1);
    }
    __shared__ float sh0[256];
    __shared__ float sh1[256];
    sh0[tid] = p0; sh1[tid] = p1;
    __syncthreads();
    for (int off = 128; off > 0; off >>= 1) {
        if (tid < off) { sh0[tid] += sh0[tid + off]; sh1[tid] += sh1[tid + off]; }
        __syncthreads();
    }
    if (tid == 0) {
        logits[b * OUTD + 0] = sh0[0];
        logits[b * OUTD + 1] = sh1[0];
    }
}

// ---------------------------------------------------------------------------
extern "C" void kernel_launch(void* const* d_in, const int* in_sizes, int n_in,
                              void* d_out, int out_size)
{
    const float* x    = (const float*)d_in[0];  // [200, 256, 3]
    const float* W    = (const float*)d_in[1];  // [2048, 2048]
    const float* Win  = (const float*)d_in[2];  // [2048, 3]
    const float* Wout = (const float*)d_in[3];  // [2, 2048]
    float* out = (float*)d_out;                 // spk [200*256*2048] | logits [256*2]

    cudaFuncSetAttribute(reservoir_kernel, cudaFuncAttributeMaxDynamicSharedMemorySize, SMEM_DYN);

    init_kernel<<<1, 32>>>();
    split_kernel<<<dim3(RES / 32, RES / 32), dim3(32, 8)>>>(W);

    dim3 grid(RES / BN, BATCH / BM);  // (32, 4) = 128 CTAs, all co-resident
    reservoir_kernel<<<grid, 256, SMEM_DYN>>>(x, Win, out);

    logits_kernel<<<BATCH, 256>>>(out, Wout, out + SPK_ELEMS);
}

// round 16
// speedup vs baseline: 6.8942x; 6.0557x over previous
#include <cuda_runtime.h>
#include <cuda_bf16.h>
#include <cstdint>

// ---------------- problem constants ----------------
#define T_STEPS 200
#define BATCH   256
#define RES     2048
#define OUTD    2
#define BETA    0.9f
#define THRESH  1.0f
#define SPK_ELEMS ((size_t)T_STEPS * BATCH * RES)
#define NSPLIT 3

// GEMM tiling: CTA 64(M) x 64(N), k-chunk 64, 256 threads (8 warps, 2x4),
// warp tile 32(M) x 16(N), mma.sync m16n8k16 bf16.
// SPARSITY: each producer CTA publishes a per-step byte flag "my 64x64 spike
// tile is nonzero" (own-byte store, parity double-buffered). Consumers ballot
// their m-group's 32 bytes into a mask and process ONLY nonzero chunks:
// zero chunks skip A/B loads, LDSMs and MMAs (exact: 0 @ W = 0).
// Pipeline is step-local: 4-slot ring (8KB A + 24KB B per slot), prologue 3
// chunks, prefetch distance 3, one commit per chunk, wait_group 0 at step end.
// Persistent kernel: one CTA/SM, grid barrier between steps, V in registers.
#define BM 64
#define BN 64
#define BK 64
#define KCHUNKS (RES / BK)              // 32
#define ROW_BYTES 4096                  // 2048 bf16 per row
#define A_STAGE 8192
#define B_STAGE 24576
#define SMEM_DYN (4 * (A_STAGE + B_STAGE))   // 131072
#define NBLK 128                        // grid size (<= SM count, co-resident)

// ---------------- device state ----------------
__device__ __nv_bfloat16 g_S[2 * BATCH * RES];          // spike double buffer
__device__ __nv_bfloat16 g_W3[(size_t)NSPLIT * RES * RES];  // split W, [s][n][k]
__device__ unsigned char g_mask[2][4][KCHUNKS];         // [parity][m_group][n_tile]
__device__ unsigned g_bar_arrive;
__device__ unsigned g_bar_gen;

// ---------------- helpers ----------------
__device__ __forceinline__ uint32_t smem_u32(const void* p) {
    uint32_t a;
    asm("{ .reg .u64 t; cvta.to.shared.u64 t, %1; cvt.u32.u64 %0, t; }" : "=r"(a) : "l"(p));
    return a;
}

__device__ __forceinline__ void ldsm4(uint32_t* r, uint32_t addr) {
    asm volatile("ldmatrix.sync.aligned.m8n8.x4.shared.b16 {%0,%1,%2,%3}, [%4];"
                 : "=r"(r[0]), "=r"(r[1]), "=r"(r[2]), "=r"(r[3]) : "r"(addr));
}

__device__ __forceinline__ void mma16816(float* c, const uint32_t* a, uint32_t b0, uint32_t b1) {
    asm("mma.sync.aligned.m16n8k16.row.col.f32.bf16.bf16.f32 "
        "{%0,%1,%2,%3}, {%4,%5,%6,%7}, {%8,%9}, {%0,%1,%2,%3};"
        : "+f"(c[0]), "+f"(c[1]), "+f"(c[2]), "+f"(c[3])
        : "r"(a[0]), "r"(a[1]), "r"(a[2]), "r"(a[3]), "r"(b0), "r"(b1));
}

#define CP_COMMIT() asm volatile("cp.async.commit_group;" ::: "memory")
#define CP_WAIT2()  asm volatile("cp.async.wait_group 2;" ::: "memory")
#define CP_WAIT0()  asm volatile("cp.async.wait_group 0;" ::: "memory")

// Grid barrier. Safe: 128 CTAs, 1/SM, all co-resident.
__device__ __forceinline__ void grid_barrier() {
    __syncthreads();
    if (threadIdx.x == 0) {
        unsigned gen;
        asm volatile("ld.acquire.gpu.global.u32 %0, [%1];" : "=r"(gen) : "l"(&g_bar_gen));
        unsigned prev;
        asm volatile("atom.add.release.gpu.global.u32 %0, [%1], %2;"
                     : "=r"(prev) : "l"(&g_bar_arrive), "r"(1u));
        if (prev == NBLK - 1) {
            asm volatile("st.relaxed.gpu.global.u32 [%0], %1;" :: "l"(&g_bar_arrive), "r"(0u));
            asm volatile("red.release.gpu.global.add.u32 [%0], %1;" :: "l"(&g_bar_gen), "r"(1u));
        } else {
            unsigned cur;
            do {
                asm volatile("ld.acquire.gpu.global.u32 %0, [%1];" : "=r"(cur) : "l"(&g_bar_gen));
            } while (cur == gen);
        }
    }
    __syncthreads();
}

// 64x64 bf16 tile (8KB): rows of 128B = 8 x 16B chunks, chunk ^= row%8 swizzle.
// 256 threads, 2 x 16B cp.async each.
__device__ __forceinline__ void load_tile256(uint32_t sbase, const char* g) {
    const int tid = threadIdx.x;
    #pragma unroll
    for (int i = 0; i < 2; i++) {
        int c = tid + i * 256;
        int row = c >> 3, ch = c & 7;
        uint32_t dst = sbase + row * 128 + ((ch ^ (row & 7)) << 4);
        const char* src = g + (size_t)row * ROW_BYTES + ch * 16;
        asm volatile("cp.async.cg.shared.global [%0], [%1], 16;" :: "r"(dst), "l"(src));
    }
}

// load A + B (3 split tiles) for one chunk into ring slot
__device__ __forceinline__ void load_chunk(uint32_t sbA, uint32_t sbB, const char* gA,
                                           const char* gB, int chunk, size_t sstr) {
    const int sl = chunk & 3;
    load_tile256(sbA + sl * A_STAGE, gA + (size_t)chunk * 128);
    #pragma unroll
    for (int s = 0; s < NSPLIT; s++)
        load_tile256(sbB + sl * B_STAGE + s * A_STAGE,
                     gB + (size_t)s * sstr + (size_t)chunk * 128);
}

// ---------------------------------------------------------------------------
__global__ void init_kernel() {
    if (threadIdx.x == 0) { g_bar_arrive = 0u; g_bar_gen = 0u; }
}

// split+transpose W: g_W3[s][n][k] = bf16 split s of W[k][n]
__global__ void split_kernel(const float* __restrict__ W) {
    __shared__ float sh[32][33];
    const int k0 = blockIdx.x * 32;
    const int n0 = blockIdx.y * 32;
    const int tx = threadIdx.x;
    const int ty = threadIdx.y;
    #pragma unroll
    for (int i = ty; i < 32; i += 8)
        sh[i][tx] = W[(size_t)(k0 + i) * RES + n0 + tx];
    __syncthreads();
    #pragma unroll
    for (int i = ty; i < 32; i += 8) {
        float w = sh[tx][i];  // = W[k0+tx][n0+i]
        __nv_bfloat16 b0 = __float2bfloat16(w);
        float r1 = w - __bfloat162float(b0);
        __nv_bfloat16 b1 = __float2bfloat16(r1);
        float r2 = r1 - __bfloat162float(b1);
        __nv_bfloat16 b2 = __float2bfloat16(r2);
        size_t o = (size_t)(n0 + i) * RES + k0 + tx;
        g_W3[o]                         = b0;
        g_W3[(size_t)RES * RES + o]     = b1;
        g_W3[(size_t)2 * RES * RES + o] = b2;
    }
}

// ---------------------------------------------------------------------------
// persistent reservoir kernel: all 200 timesteps, grid barrier between steps,
// per-tile sparsity masks to skip all-zero spike chunks (exact).
// ---------------------------------------------------------------------------
__global__ void __launch_bounds__(256, 1)
reservoir_kernel(const float* __restrict__ x,
                 const float* __restrict__ Win,
                 float* __restrict__ out)
{
    extern __shared__ __align__(128) char dsm[];

    const int tid  = threadIdx.x;
    const int lane = tid & 31;
    const int warp = tid >> 5;
    const int n0 = blockIdx.x * BN;
    const int m0 = blockIdx.y * BM;
    const int wm = warp >> 2;        // 0..1 -> m offset *32
    const int wn = warp & 3;         // 0..3 -> n offset *16
    const int grp  = lane >> 3;      // ldmatrix address group
    const int lrow = lane & 7;
    const int lr = lane >> 2;        // mma frag row
    const int lc = lane & 3;         // mma frag col pair

    const uint32_t sbA = smem_u32(dsm);          // 4 x 8KB A slots
    const uint32_t sbB = sbA + 4 * A_STAGE;      // 4 x 24KB B slots
    const char* gB = (const char*)g_W3 + (size_t)n0 * ROW_BYTES;
    const size_t SSTR = (size_t)RES * RES * 2;   // split stride (bytes)

    // this thread's 4 epilogue n-columns: wn*16 + nt*8 + lc*2 + {0,1}
    float wv[4][3];
    #pragma unroll
    for (int nt = 0; nt < 2; nt++)
        #pragma unroll
        for (int q = 0; q < 2; q++) {
            const int nl = wn * 16 + nt * 8 + lc * 2 + q;
            wv[nt * 2 + q][0] = Win[(n0 + nl) * 3 + 0];
            wv[nt * 2 + q][1] = Win[(n0 + nl) * 3 + 1];
            wv[nt * 2 + q][2] = Win[(n0 + nl) * 3 + 2];
        }

    // ldmatrix per-thread row bases (constant across steps)
    const int rowA0 = wm * 32 + (grp & 1) * 8 + lrow;
    const int rowA1 = rowA0 + 16;
    const int rowB  = wn * 16 + (grp >> 1) * 8 + lrow;
    const uint32_t aOff0 = rowA0 * 128, aOff1 = rowA1 * 128, bOff = rowB * 128;
    const int a7_0 = rowA0 & 7, a7_1 = rowA1 & 7, b7 = rowB & 7;
    const int akh = grp >> 1, bkh = grp & 1;

    // membrane potential in registers: V[mi][r][nt][2]
    float V[2][2][2][2];
    #pragma unroll
    for (int a = 0; a < 2; a++)
        #pragma unroll
        for (int b = 0; b < 2; b++)
            #pragma unroll
            for (int c = 0; c < 2; c++)
                V[a][b][c][0] = V[a][b][c][1] = 0.0f;

    #pragma unroll 1
    for (int t = 0; t < T_STEPS; t++) {
        float acc[2][2][4];
        #pragma unroll
        for (int a = 0; a < 2; a++)
            #pragma unroll
            for (int b = 0; b < 2; b++)
                #pragma unroll
                for (int c = 0; c < 4; c++) acc[a][b][c] = 0.0f;

        // ---- read this m-group's sparsity mask (written at step t-1) ----
        uint32_t mask = 0;
        if (t > 0) {
            const unsigned char* mb = &g_mask[(t + 1) & 1][blockIdx.y][0];
            unsigned char myb = mb[lane];                       // lanes 0..31
            mask = __ballot_sync(0xFFFFFFFFu, myb != 0);        // uniform per warp
        }

        if (mask != 0) {
            const char* gA = (const char*)g_S
                + (size_t)((t + 1) & 1) * BATCH * RES * 2 + (size_t)m0 * ROW_BYTES;

            // prologue: chunks 0..2 (gated); one commit each (empty ok)
            #pragma unroll
            for (int p = 0; p < 3; p++) {
                if ((mask >> p) & 1) load_chunk(sbA, sbB, gA, gB, p, SSTR);
                CP_COMMIT();
            }

            #pragma unroll 1
            for (int c = 0; c < KCHUNKS; c++) {
                CP_WAIT2();
                __syncthreads();

                if ((mask >> c) & 1) {
                    const uint32_t aT = sbA + (c & 3) * A_STAGE;
                    const uint32_t bT = sbB + (c & 3) * B_STAGE;
                    #pragma unroll
                    for (int kk = 0; kk < 4; kk++) {
                        uint32_t a0[4], a1[4];
                        ldsm4(a0, aT + aOff0 + ((((kk << 1) | akh) ^ a7_0) << 4));
                        ldsm4(a1, aT + aOff1 + ((((kk << 1) | akh) ^ a7_1) << 4));
                        #pragma unroll
                        for (int s = 0; s < NSPLIT; s++) {
                            uint32_t bb[4];
                            ldsm4(bb, bT + s * A_STAGE + bOff + ((((kk << 1) | bkh) ^ b7) << 4));
                            mma16816(acc[0][0], a0, bb[0], bb[1]);
                            mma16816(acc[0][1], a0, bb[2], bb[3]);
                            mma16816(acc[1][0], a1, bb[0], bb[1]);
                            mma16816(acc[1][1], a1, bb[2], bb[3]);
                        }
                    }
                }

                const int cn = c + 3;
                if (cn < KCHUNKS && ((mask >> cn) & 1))
                    load_chunk(sbA, sbB, gA, gB, cn, SSTR);
                CP_COMMIT();   // unconditional: keeps group counting exact
            }
            CP_WAIT0();        // drain: every step starts with 0 groups in flight
        }

        __syncthreads();

        // ---- fused LIF epilogue (V in registers, Win in registers) ----
        const float* xt = x + (size_t)t * BATCH * 3;
        float*         outT = out + (size_t)t * BATCH * RES;
        __nv_bfloat16* Sw   = g_S + (size_t)(t & 1) * BATCH * RES;
        float anyspk = 0.0f;

        #pragma unroll
        for (int mi = 0; mi < 2; mi++) {
            #pragma unroll
            for (int r = 0; r < 2; r++) {
                const int b = m0 + wm * 32 + mi * 16 + r * 8 + lr;
                const float x0 = xt[b * 3 + 0];
                const float x1 = xt[b * 3 + 1];
                const float x2 = xt[b * 3 + 2];
                #pragma unroll
                for (int nt = 0; nt < 2; nt++) {
                    const int nl = wn * 16 + nt * 8 + lc * 2;
                    const size_t vi = (size_t)b * RES + n0 + nl;
                    const float inj0 = x0 * wv[nt * 2 + 0][0] + x1 * wv[nt * 2 + 0][1] + x2 * wv[nt * 2 + 0][2];
                    const float inj1 = x0 * wv[nt * 2 + 1][0] + x1 * wv[nt * 2 + 1][1] + x2 * wv[nt * 2 + 1][2];
                    const float y0 = BETA * V[mi][r][nt][0] + inj0 + acc[mi][nt][r * 2 + 0];
                    const float y1 = BETA * V[mi][r][nt][1] + inj1 + acc[mi][nt][r * 2 + 1];
                    const float s0 = (y0 >= THRESH) ? 1.0f : 0.0f;
                    const float s1 = (y1 >= THRESH) ? 1.0f : 0.0f;
                    V[mi][r][nt][0] = (y0 >= THRESH) ? 0.0f : y0;
                    V[mi][r][nt][1] = (y1 >= THRESH) ? 0.0f : y1;
                    anyspk += s0 + s1;
                    float2 sp; sp.x = s0; sp.y = s1;
                    *(float2*)&outT[vi] = sp;
                    __nv_bfloat162 sb2;
                    sb2.x = __float2bfloat16(s0);
                    sb2.y = __float2bfloat16(s1);
                    *(__nv_bfloat162*)&Sw[vi] = sb2;
                }
            }
        }

        // ---- publish this tile's nonzero flag (own byte, parity t&1) ----
        const int any = __syncthreads_or(anyspk > 0.0f ? 1 : 0);
        if (tid == 0)
            g_mask[t & 1][blockIdx.y][blockIdx.x] = (unsigned char)(any ? 1 : 0);

        if (t < T_STEPS - 1)
            grid_barrier();   // spike slab + mask byte published before t+1
    }
}

// ---------------------------------------------------------------------------
__global__ void __launch_bounds__(256)
logits_kernel(const float* __restrict__ spk,
              const float* __restrict__ Wout,
              float* __restrict__ logits)
{
    const int b = blockIdx.x;
    const int tid = threadIdx.x;
    float p0 = 0.0f, p1 = 0.0f;
    for (int r = tid; r < RES; r += 256) {
        float s = 0.0f;
        #pragma unroll
        for (int tt = 0; tt < 10; tt++)
            s += spk[((size_t)(T_STEPS - 10 + tt) * BATCH + b) * RES + r];
        s *= 0.1f;
        p0 = fmaf(s, Wout[r], p0);
        p1 = fmaf(s, Wout[RES + r], p1);
    }
    __shared__ float sh0[256];
    __shared__ float sh1[256];
    sh0[tid] = p0; sh1[tid] = p1;
    __syncthreads();
    for (int off = 128; off > 0; off >>= 1) {
        if (tid < off) { sh0[tid] += sh0[tid + off]; sh1[tid] += sh1[tid + off]; }
        __syncthreads();
    }
    if (tid == 0) {
        logits[b * OUTD + 0] = sh0[0];
        logits[b * OUTD + 1] = sh1[0];
    }
}

// ---------------------------------------------------------------------------
extern "C" void kernel_launch(void* const* d_in, const int* in_sizes, int n_in,
                              void* d_out, int out_size)
{
    const float* x    = (const float*)d_in[0];  // [200, 256, 3]
    const float* W    = (const float*)d_in[1];  // [2048, 2048]
    const float* Win  = (const float*)d_in[2];  // [2048, 3]
    const float* Wout = (const float*)d_in[3];  // [2, 2048]
    float* out = (float*)d_out;                 // spk [200*256*2048] | logits [256*2]

    cudaFuncSetAttribute(reservoir_kernel, cudaFuncAttributeMaxDynamicSharedMemorySize, SMEM_DYN);

    init_kernel<<<1, 32>>>();
    split_kernel<<<dim3(RES / 32, RES / 32), dim3(32, 8)>>>(W);

    dim3 grid(RES / BN, BATCH / BM);  // (32, 4) = 128 CTAs, all co-resident
    reservoir_kernel<<<grid, 256, SMEM_DYN>>>(x, Win, out);

    logits_kernel<<<BATCH, 256>>>(out, Wout, out + SPK_ELEMS);
}

// round 17
// speedup vs baseline: 6.9107x; 1.0024x over previous
#include <cuda_runtime.h>
#include <cuda_bf16.h>
#include <cstdint>

// ---------------- problem constants ----------------
#define T_STEPS 200
#define BATCH   256
#define RES     2048
#define OUTD    2
#define BETA    0.9f
#define THRESH  1.0f
#define SPK_ELEMS ((size_t)T_STEPS * BATCH * RES)
#define NSPLIT 3

// GEMM tiling: CTA 64(M) x 64(N), k-chunk 64, 256 threads (8 warps, 2x4),
// warp tile 32(M) x 16(N), mma.sync m16n8k16 bf16.
// SPARSITY: each producer CTA publishes a per-step byte flag "my 64x64 spike
// tile is nonzero" (own-byte store, parity double-buffered). Consumers ballot
// their m-group's 32 bytes into a mask and process ONLY nonzero chunks:
// zero chunks skip A/B loads, LDSMs and MMAs (exact: 0 @ W = 0).
// Pipeline is step-local: 4-slot ring (8KB A + 24KB B per slot), prologue 3
// chunks, prefetch distance 3, one commit per chunk, wait_group 0 at step end.
// Persistent kernel: one CTA/SM, grid barrier between steps, V in registers.
#define BM 64
#define BN 64
#define BK 64
#define KCHUNKS (RES / BK)              // 32
#define ROW_BYTES 4096                  // 2048 bf16 per row
#define A_STAGE 8192
#define B_STAGE 24576
#define SMEM_DYN (4 * (A_STAGE + B_STAGE))   // 131072
#define NBLK 128                        // grid size (<= SM count, co-resident)

// ---------------- device state ----------------
__device__ __nv_bfloat16 g_S[2 * BATCH * RES];          // spike double buffer
__device__ __nv_bfloat16 g_W3[(size_t)NSPLIT * RES * RES];  // split W, [s][n][k]
__device__ unsigned char g_mask[2][4][KCHUNKS];         // [parity][m_group][n_tile]
__device__ unsigned g_bar_arrive;
__device__ unsigned g_bar_gen;

// ---------------- helpers ----------------
__device__ __forceinline__ uint32_t smem_u32(const void* p) {
    uint32_t a;
    asm("{ .reg .u64 t; cvta.to.shared.u64 t, %1; cvt.u32.u64 %0, t; }" : "=r"(a) : "l"(p));
    return a;
}

__device__ __forceinline__ void ldsm4(uint32_t* r, uint32_t addr) {
    asm volatile("ldmatrix.sync.aligned.m8n8.x4.shared.b16 {%0,%1,%2,%3}, [%4];"
                 : "=r"(r[0]), "=r"(r[1]), "=r"(r[2]), "=r"(r[3]) : "r"(addr));
}

__device__ __forceinline__ void mma16816(float* c, const uint32_t* a, uint32_t b0, uint32_t b1) {
    asm("mma.sync.aligned.m16n8k16.row.col.f32.bf16.bf16.f32 "
        "{%0,%1,%2,%3}, {%4,%5,%6,%7}, {%8,%9}, {%0,%1,%2,%3};"
        : "+f"(c[0]), "+f"(c[1]), "+f"(c[2]), "+f"(c[3])
        : "r"(a[0]), "r"(a[1]), "r"(a[2]), "r"(a[3]), "r"(b0), "r"(b1));
}

#define CP_COMMIT() asm volatile("cp.async.commit_group;" ::: "memory")
#define CP_WAIT2()  asm volatile("cp.async.wait_group 2;" ::: "memory")
#define CP_WAIT0()  asm volatile("cp.async.wait_group 0;" ::: "memory")

// Grid barrier. Safe: 128 CTAs, 1/SM, all co-resident.
__device__ __forceinline__ void grid_barrier() {
    __syncthreads();
    if (threadIdx.x == 0) {
        unsigned gen;
        asm volatile("ld.acquire.gpu.global.u32 %0, [%1];" : "=r"(gen) : "l"(&g_bar_gen));
        unsigned prev;
        asm volatile("atom.add.release.gpu.global.u32 %0, [%1], %2;"
                     : "=r"(prev) : "l"(&g_bar_arrive), "r"(1u));
        if (prev == NBLK - 1) {
            asm volatile("st.relaxed.gpu.global.u32 [%0], %1;" :: "l"(&g_bar_arrive), "r"(0u));
            asm volatile("red.release.gpu.global.add.u32 [%0], %1;" :: "l"(&g_bar_gen), "r"(1u));
        } else {
            unsigned cur;
            do {
                asm volatile("ld.acquire.gpu.global.u32 %0, [%1];" : "=r"(cur) : "l"(&g_bar_gen));
            } while (cur == gen);
        }
    }
    __syncthreads();
}

// 64x64 bf16 tile (8KB): rows of 128B = 8 x 16B chunks, chunk ^= row%8 swizzle.
// 256 threads, 2 x 16B cp.async each.
__device__ __forceinline__ void load_tile256(uint32_t sbase, const char* g) {
    const int tid = threadIdx.x;
    #pragma unroll
    for (int i = 0; i < 2; i++) {
        int c = tid + i * 256;
        int row = c >> 3, ch = c & 7;
        uint32_t dst = sbase + row * 128 + ((ch ^ (row & 7)) << 4);
        const char* src = g + (size_t)row * ROW_BYTES + ch * 16;
        asm volatile("cp.async.cg.shared.global [%0], [%1], 16;" :: "r"(dst), "l"(src));
    }
}

// load A + B (3 split tiles) for one chunk into ring slot
__device__ __forceinline__ void load_chunk(uint32_t sbA, uint32_t sbB, const char* gA,
                                           const char* gB, int chunk, size_t sstr) {
    const int sl = chunk & 3;
    load_tile256(sbA + sl * A_STAGE, gA + (size_t)chunk * 128);
    #pragma unroll
    for (int s = 0; s < NSPLIT; s++)
        load_tile256(sbB + sl * B_STAGE + s * A_STAGE,
                     gB + (size_t)s * sstr + (size_t)chunk * 128);
}

// ---------------------------------------------------------------------------
__global__ void init_kernel() {
    if (threadIdx.x == 0) { g_bar_arrive = 0u; g_bar_gen = 0u; }
}

// split+transpose W: g_W3[s][n][k] = bf16 split s of W[k][n]
__global__ void split_kernel(const float* __restrict__ W) {
    __shared__ float sh[32][33];
    const int k0 = blockIdx.x * 32;
    const int n0 = blockIdx.y * 32;
    const int tx = threadIdx.x;
    const int ty = threadIdx.y;
    #pragma unroll
    for (int i = ty; i < 32; i += 8)
        sh[i][tx] = W[(size_t)(k0 + i) * RES + n0 + tx];
    __syncthreads();
    #pragma unroll
    for (int i = ty; i < 32; i += 8) {
        float w = sh[tx][i];  // = W[k0+tx][n0+i]
        __nv_bfloat16 b0 = __float2bfloat16(w);
        float r1 = w - __bfloat162float(b0);
        __nv_bfloat16 b1 = __float2bfloat16(r1);
        float r2 = r1 - __bfloat162float(b1);
        __nv_bfloat16 b2 = __float2bfloat16(r2);
        size_t o = (size_t)(n0 + i) * RES + k0 + tx;
        g_W3[o]                         = b0;
        g_W3[(size_t)RES * RES + o]     = b1;
        g_W3[(size_t)2 * RES * RES + o] = b2;
    }
}

// ---------------------------------------------------------------------------
// persistent reservoir kernel: all 200 timesteps, grid barrier between steps,
// per-tile sparsity masks to skip all-zero spike chunks (exact).
// ---------------------------------------------------------------------------
__global__ void __launch_bounds__(256, 1)
reservoir_kernel(const float* __restrict__ x,
                 const float* __restrict__ Win,
                 float* __restrict__ out)
{
    extern __shared__ __align__(128) char dsm[];

    const int tid  = threadIdx.x;
    const int lane = tid & 31;
    const int warp = tid >> 5;
    const int n0 = blockIdx.x * BN;
    const int m0 = blockIdx.y * BM;
    const int wm = warp >> 2;        // 0..1 -> m offset *32
    const int wn = warp & 3;         // 0..3 -> n offset *16
    const int grp  = lane >> 3;      // ldmatrix address group
    const int lrow = lane & 7;
    const int lr = lane >> 2;        // mma frag row
    const int lc = lane & 3;         // mma frag col pair

    const uint32_t sbA = smem_u32(dsm);          // 4 x 8KB A slots
    const uint32_t sbB = sbA + 4 * A_STAGE;      // 4 x 24KB B slots
    const char* gB = (const char*)g_W3 + (size_t)n0 * ROW_BYTES;
    const size_t SSTR = (size_t)RES * RES * 2;   // split stride (bytes)

    // this thread's 4 epilogue n-columns: wn*16 + nt*8 + lc*2 + {0,1}
    float wv[4][3];
    #pragma unroll
    for (int nt = 0; nt < 2; nt++)
        #pragma unroll
        for (int q = 0; q < 2; q++) {
            const int nl = wn * 16 + nt * 8 + lc * 2 + q;
            wv[nt * 2 + q][0] = Win[(n0 + nl) * 3 + 0];
            wv[nt * 2 + q][1] = Win[(n0 + nl) * 3 + 1];
            wv[nt * 2 + q][2] = Win[(n0 + nl) * 3 + 2];
        }

    // ldmatrix per-thread row bases (constant across steps)
    const int rowA0 = wm * 32 + (grp & 1) * 8 + lrow;
    const int rowA1 = rowA0 + 16;
    const int rowB  = wn * 16 + (grp >> 1) * 8 + lrow;
    const uint32_t aOff0 = rowA0 * 128, aOff1 = rowA1 * 128, bOff = rowB * 128;
    const int a7_0 = rowA0 & 7, a7_1 = rowA1 & 7, b7 = rowB & 7;
    const int akh = grp >> 1, bkh = grp & 1;

    // membrane potential in registers: V[mi][r][nt][2]
    float V[2][2][2][2];
    #pragma unroll
    for (int a = 0; a < 2; a++)
        #pragma unroll
        for (int b = 0; b < 2; b++)
            #pragma unroll
            for (int c = 0; c < 2; c++)
                V[a][b][c][0] = V[a][b][c][1] = 0.0f;

    #pragma unroll 1
    for (int t = 0; t < T_STEPS; t++) {
        float acc[2][2][4];
        #pragma unroll
        for (int a = 0; a < 2; a++)
            #pragma unroll
            for (int b = 0; b < 2; b++)
                #pragma unroll
                for (int c = 0; c < 4; c++) acc[a][b][c] = 0.0f;

        // ---- read this m-group's sparsity mask (written at step t-1) ----
        uint32_t mask = 0;
        if (t > 0) {
            const unsigned char* mb = &g_mask[(t + 1) & 1][blockIdx.y][0];
            unsigned char myb = mb[lane];                       // lanes 0..31
            mask = __ballot_sync(0xFFFFFFFFu, myb != 0);        // uniform per warp
        }

        if (mask != 0) {
            const char* gA = (const char*)g_S
                + (size_t)((t + 1) & 1) * BATCH * RES * 2 + (size_t)m0 * ROW_BYTES;

            // prologue: chunks 0..2 (gated); one commit each (empty ok)
            #pragma unroll
            for (int p = 0; p < 3; p++) {
                if ((mask >> p) & 1) load_chunk(sbA, sbB, gA, gB, p, SSTR);
                CP_COMMIT();
            }

            #pragma unroll 1
            for (int c = 0; c < KCHUNKS; c++) {
                CP_WAIT2();
                __syncthreads();

                if ((mask >> c) & 1) {
                    const uint32_t aT = sbA + (c & 3) * A_STAGE;
                    const uint32_t bT = sbB + (c & 3) * B_STAGE;
                    #pragma unroll
                    for (int kk = 0; kk < 4; kk++) {
                        uint32_t a0[4], a1[4];
                        ldsm4(a0, aT + aOff0 + ((((kk << 1) | akh) ^ a7_0) << 4));
                        ldsm4(a1, aT + aOff1 + ((((kk << 1) | akh) ^ a7_1) << 4));
                        #pragma unroll
                        for (int s = 0; s < NSPLIT; s++) {
                            uint32_t bb[4];
                            ldsm4(bb, bT + s * A_STAGE + bOff + ((((kk << 1) | bkh) ^ b7) << 4));
                            mma16816(acc[0][0], a0, bb[0], bb[1]);
                            mma16816(acc[0][1], a0, bb[2], bb[3]);
                            mma16816(acc[1][0], a1, bb[0], bb[1]);
                            mma16816(acc[1][1], a1, bb[2], bb[3]);
                        }
                    }
                }

                const int cn = c + 3;
                if (cn < KCHUNKS && ((mask >> cn) & 1))
                    load_chunk(sbA, sbB, gA, gB, cn, SSTR);
                CP_COMMIT();   // unconditional: keeps group counting exact
            }
            CP_WAIT0();        // drain: every step starts with 0 groups in flight
        }

        __syncthreads();

        // ---- fused LIF epilogue (V in registers, Win in registers) ----
        const float* xt = x + (size_t)t * BATCH * 3;
        float*         outT = out + (size_t)t * BATCH * RES;
        __nv_bfloat16* Sw   = g_S + (size_t)(t & 1) * BATCH * RES;
        float anyspk = 0.0f;

        #pragma unroll
        for (int mi = 0; mi < 2; mi++) {
            #pragma unroll
            for (int r = 0; r < 2; r++) {
                const int b = m0 + wm * 32 + mi * 16 + r * 8 + lr;
                const float x0 = xt[b * 3 + 0];
                const float x1 = xt[b * 3 + 1];
                const float x2 = xt[b * 3 + 2];
                #pragma unroll
                for (int nt = 0; nt < 2; nt++) {
                    const int nl = wn * 16 + nt * 8 + lc * 2;
                    const size_t vi = (size_t)b * RES + n0 + nl;
                    const float inj0 = x0 * wv[nt * 2 + 0][0] + x1 * wv[nt * 2 + 0][1] + x2 * wv[nt * 2 + 0][2];
                    const float inj1 = x0 * wv[nt * 2 + 1][0] + x1 * wv[nt * 2 + 1][1] + x2 * wv[nt * 2 + 1][2];
                    const float y0 = BETA * V[mi][r][nt][0] + inj0 + acc[mi][nt][r * 2 + 0];
                    const float y1 = BETA * V[mi][r][nt][1] + inj1 + acc[mi][nt][r * 2 + 1];
                    const float s0 = (y0 >= THRESH) ? 1.0f : 0.0f;
                    const float s1 = (y1 >= THRESH) ? 1.0f : 0.0f;
                    V[mi][r][nt][0] = (y0 >= THRESH) ? 0.0f : y0;
                    V[mi][r][nt][1] = (y1 >= THRESH) ? 0.0f : y1;
                    anyspk += s0 + s1;
                    float2 sp; sp.x = s0; sp.y = s1;
                    *(float2*)&outT[vi] = sp;
                    __nv_bfloat162 sb2;
                    sb2.x = __float2bfloat16(s0);
                    sb2.y = __float2bfloat16(s1);
                    *(__nv_bfloat162*)&Sw[vi] = sb2;
                }
            }
        }

        // ---- publish this tile's nonzero flag (own byte, parity t&1) ----
        const int any = __syncthreads_or(anyspk > 0.0f ? 1 : 0);
        if (tid == 0)
            g_mask[t & 1][blockIdx.y][blockIdx.x] = (unsigned char)(any ? 1 : 0);

        if (t < T_STEPS - 1)
            grid_barrier();   // spike slab + mask byte published before t+1
    }
}

// ---------------------------------------------------------------------------
__global__ void __launch_bounds__(256)
logits_kernel(const float* __restrict__ spk,
              const float* __restrict__ Wout,
              float* __restrict__ logits)
{
    const int b = blockIdx.x;
    const int tid = threadIdx.x;
    float p0 = 0.0f, p1 = 0.0f;
    for (int r = tid; r < RES; r += 256) {
        float s = 0.0f;
        #pragma unroll
        for (int tt = 0; tt < 10; tt++)
            s += spk[((size_t)(T_STEPS - 10 + tt) * BATCH + b) * RES + r];
        s *= 0.1f;
        p0 = fmaf(s, Wout[r], p0);
        p1 = fmaf(s, Wout[RES + r], p1);
    }
    __shared__ float sh0[256];
    __shared__ float sh1[256];
    sh0[tid] = p0; sh1[tid] = p1;
    __syncthreads();
    for (int off = 128; off > 0; off >>= 1) {
        if (tid < off) { sh0[tid] += sh0[tid + off]; sh1[tid] += sh1[tid + off]; }
        __syncthreads();
    }
    if (tid == 0) {
        logits[b * OUTD + 0] = sh0[0];
        logits[b * OUTD + 1] = sh1[0];
    }
}

// ---------------------------------------------------------------------------
extern "C" void kernel_launch(void* const* d_in, const int* in_sizes, int n_in,
                              void* d_out, int out_size)
{
    const float* x    = (const float*)d_in[0];  // [200, 256, 3]
    const float* W    = (const float*)d_in[1];  // [2048, 2048]
    const float* Win  = (const float*)d_in[2];  // [2048, 3]
    const float* Wout = (const float*)d_in[3];  // [2, 2048]
    float* out = (float*)d_out;                 // spk [200*256*2048] | logits [256*2]

    cudaFuncSetAttribute(reservoir_kernel, cudaFuncAttributeMaxDynamicSharedMemorySize, SMEM_DYN);

    init_kernel<<<1, 32>>>();
    split_kernel<<<dim3(RES / 32, RES / 32), dim3(32, 8)>>>(W);

    dim3 grid(RES / BN, BATCH / BM);  // (32, 4) = 128 CTAs, all co-resident
    reservoir_kernel<<<grid, 256, SMEM_DYN>>>(x, Win, out);

    logits_kernel<<<BATCH, 256>>>(out, Wout, out + SPK_ELEMS);
}